// round 1
// baseline (speedup 1.0000x reference)
#include <cuda_runtime.h>
#include <cuda_bf16.h>

#define D_TOTAL   8388608
#define TABLE_N   1024
#define NBLOCKS   1184
#define NTHREADS  256

__device__ float g_partials[NBLOCKS];

__global__ __launch_bounds__(NTHREADS) void phasecell_main(
    const int* __restrict__ ctx_phase,
    const int* __restrict__ ctx_mag,
    const int* __restrict__ self_phase,
    const int* __restrict__ self_mag,
    const float* __restrict__ cos_table,
    const float* __restrict__ exp_table,
    const float* __restrict__ cos_grad_table,
    const float* __restrict__ exp_grad_table,
    float* __restrict__ out)
{
    __shared__ float2 phase_tab[TABLE_N];  // (cos, dcos)
    __shared__ float2 mag_tab[TABLE_N];    // (exp, dexp)
    __shared__ float red[NTHREADS / 32];

    const int tid = threadIdx.x;
    for (int i = tid; i < TABLE_N; i += NTHREADS) {
        phase_tab[i] = make_float2(cos_table[i], cos_grad_table[i]);
        mag_tab[i]   = make_float2(exp_table[i], exp_grad_table[i]);
    }
    __syncthreads();

    const int4* cp4 = (const int4*)ctx_phase;
    const int4* sp4 = (const int4*)self_phase;
    const int4* cm4 = (const int4*)ctx_mag;
    const int4* sm4 = (const int4*)self_mag;

    float* __restrict__ out_phase = out;
    float* __restrict__ out_mag   = out + (size_t)D_TOTAL;
    float* __restrict__ out_sig   = out + (size_t)2 * D_TOTAL;
    float* __restrict__ out_gp    = out + (size_t)3 * D_TOTAL + 1;
    float* __restrict__ out_gm    = out + (size_t)4 * D_TOTAL + 1;

    const int nvec = D_TOTAL / 4;
    float acc = 0.0f;

    for (int v = blockIdx.x * NTHREADS + tid; v < nvec; v += gridDim.x * NTHREADS) {
        int4 a = cp4[v];
        int4 b = sp4[v];
        int4 c = cm4[v];
        int4 d = sm4[v];

        int p0 = (a.x + b.x) & (TABLE_N - 1);
        int p1 = (a.y + b.y) & (TABLE_N - 1);
        int p2 = (a.z + b.z) & (TABLE_N - 1);
        int p3 = (a.w + b.w) & (TABLE_N - 1);
        int m0 = (c.x + d.x) & (TABLE_N - 1);
        int m1 = (c.y + d.y) & (TABLE_N - 1);
        int m2 = (c.z + d.z) & (TABLE_N - 1);
        int m3 = (c.w + d.w) & (TABLE_N - 1);

        float2 ph0 = phase_tab[p0], ph1 = phase_tab[p1];
        float2 ph2 = phase_tab[p2], ph3 = phase_tab[p3];
        float2 mg0 = mag_tab[m0],   mg1 = mag_tab[m1];
        float2 mg2 = mag_tab[m2],   mg3 = mag_tab[m3];

        float s0 = ph0.x * mg0.x;
        float s1 = ph1.x * mg1.x;
        float s2 = ph2.x * mg2.x;
        float s3 = ph3.x * mg3.x;
        acc += (s0 + s1) + (s2 + s3);

        ((float4*)out_phase)[v] = make_float4((float)p0, (float)p1, (float)p2, (float)p3);
        ((float4*)out_mag)[v]   = make_float4((float)m0, (float)m1, (float)m2, (float)m3);
        ((float4*)out_sig)[v]   = make_float4(s0, s1, s2, s3);

        // grad arrays start at a 4B-misaligned offset (3D+1) -> scalar stores
        int base = v * 4;
        out_gp[base + 0] = ph0.y * mg0.x;
        out_gp[base + 1] = ph1.y * mg1.x;
        out_gp[base + 2] = ph2.y * mg2.x;
        out_gp[base + 3] = ph3.y * mg3.x;
        out_gm[base + 0] = ph0.x * mg0.y;
        out_gm[base + 1] = ph1.x * mg1.y;
        out_gm[base + 2] = ph2.x * mg2.y;
        out_gm[base + 3] = ph3.x * mg3.y;
    }

    // Deterministic block reduction (fixed order within warp + across warps)
    #pragma unroll
    for (int off = 16; off > 0; off >>= 1)
        acc += __shfl_down_sync(0xFFFFFFFFu, acc, off);
    if ((tid & 31) == 0) red[tid >> 5] = acc;
    __syncthreads();
    if (tid == 0) {
        float s = 0.0f;
        #pragma unroll
        for (int w = 0; w < NTHREADS / 32; w++) s += red[w];
        g_partials[blockIdx.x] = s;
    }
}

__global__ __launch_bounds__(256) void phasecell_reduce(float* __restrict__ out)
{
    __shared__ float red[8];
    const int tid = threadIdx.x;
    float a = 0.0f;
    for (int i = tid; i < NBLOCKS; i += 256) a += g_partials[i];
    #pragma unroll
    for (int off = 16; off > 0; off >>= 1)
        a += __shfl_down_sync(0xFFFFFFFFu, a, off);
    if ((tid & 31) == 0) red[tid >> 5] = a;
    __syncthreads();
    if (tid == 0) {
        float s = 0.0f;
        #pragma unroll
        for (int w = 0; w < 8; w++) s += red[w];
        out[(size_t)3 * D_TOTAL] = s;  // strength scalar
    }
}

extern "C" void kernel_launch(void* const* d_in, const int* in_sizes, int n_in,
                              void* d_out, int out_size)
{
    // metadata order: ctx_phase_idx, ctx_mag_idx, self_phase_idx, self_mag_idx,
    //                 cos_table, exp_table, cos_grad_table, exp_grad_table
    const int*   ctx_phase  = (const int*)d_in[0];
    const int*   ctx_mag    = (const int*)d_in[1];
    const int*   self_phase = (const int*)d_in[2];
    const int*   self_mag   = (const int*)d_in[3];
    const float* cos_t      = (const float*)d_in[4];
    const float* exp_t      = (const float*)d_in[5];
    const float* cos_g      = (const float*)d_in[6];
    const float* exp_g      = (const float*)d_in[7];
    float* out = (float*)d_out;

    phasecell_main<<<NBLOCKS, NTHREADS>>>(ctx_phase, ctx_mag, self_phase, self_mag,
                                          cos_t, exp_t, cos_g, exp_g, out);
    phasecell_reduce<<<1, 256>>>(out);
}